// round 10
// baseline (speedup 1.0000x reference)
#include <cuda_runtime.h>
#include <cuda_bf16.h>
#include <cstdint>

#define BATCH 8
#define CIN 256
#define COUT 128
#define HIN 60
#define WIN 80
#define HUP 122
#define HOUT 120
#define WOUT 160
#define NPIX (HOUT*WOUT)   // 19200

// ---------------------------------------------------------------------------
// Device-global scratch
// ---------------------------------------------------------------------------
__device__ __align__(16) float         g_dw[(size_t)BATCH * CIN * NPIX]; // [b][c][p]
__device__ __align__(16) __nv_bfloat16 g_Ah[COUT * CIN];                 // pw hi [o][c]
__device__ __align__(16) __nv_bfloat16 g_Al[COUT * CIN];                 // pw lo [o][c]

// ---------------------------------------------------------------------------
// Kernel: split pointwise weights [o][c] fp32 -> bf16 hi/lo
// ---------------------------------------------------------------------------
__global__ void pwsplit_kernel(const float* __restrict__ pw) {
    int i = blockIdx.x * 256 + threadIdx.x;          // 0..32767
    float v = pw[i];
    __nv_bfloat16 h = __float2bfloat16(v);
    __nv_bfloat16 l = __float2bfloat16(v - __bfloat162float(h));
    g_Ah[i] = h;
    g_Al[i] = l;
}

// ---------------------------------------------------------------------------
// Kernel: bilinear upsample (align_corners) + 3x3 depthwise VALID
// ---------------------------------------------------------------------------
__global__ __launch_bounds__(256) void dw_kernel(const float* __restrict__ x,
                                                 const float* __restrict__ wdw) {
    __shared__ float vs[HUP * WIN];                  // 39040 B
    __shared__ float fxs[162];
    __shared__ int   x0s[162];

    int bc = blockIdx.x;
    int c  = bc & (CIN - 1);
    const float* xp = x + (size_t)bc * (HIN * WIN);
    float* op = g_dw + (size_t)bc * NPIX;
    int tid = threadIdx.x;

    const float SY = (float)(59.0 / 121.0);
    const float SX = (float)(79.0 / 161.0);

    if (tid < 162) {
        float wx  = tid * SX;
        float x0f = floorf(wx);
        fxs[tid] = wx - x0f;
        x0s[tid] = (int)x0f;
    }

    for (int i = tid; i < HUP * WIN; i += 256) {
        int rr = i / WIN;
        int xc = i - rr * WIN;
        float hy  = rr * SY;
        float y0f = floorf(hy);
        int   y0  = (int)y0f;
        float fy  = hy - y0f;
        int   y1  = y0 + 1; if (y1 > HIN - 1) y1 = HIN - 1;
        float a  = xp[y0 * WIN + xc];
        float b2 = xp[y1 * WIN + xc];
        vs[i] = a + fy * (b2 - a);
    }

    float kd[9];
#pragma unroll
    for (int t = 0; t < 9; t++) kd[t] = __ldg(wdw + c * 9 + t);

    __syncthreads();

    for (int s = tid; s < 2400; s += 256) {
        int h  = s / 20;
        int w0 = (s - h * 20) * 8;

        float u[3][10];
#pragma unroll
        for (int j = 0; j < 10; j++) {
            int   cc = w0 + j;
            int   x0 = x0s[cc];
            float fx = fxs[cc];
#pragma unroll
            for (int i2 = 0; i2 < 3; i2++) {
                const float* vr = vs + (h + i2) * WIN;
                float a  = vr[x0];
                float b2 = vr[x0 + 1];
                u[i2][j] = a + fx * (b2 - a);
            }
        }

        float res[8];
#pragma unroll
        for (int ww = 0; ww < 8; ww++) {
            float acc = 0.0f;
#pragma unroll
            for (int i2 = 0; i2 < 3; i2++)
#pragma unroll
                for (int j = 0; j < 3; j++)
                    acc = fmaf(kd[i2 * 3 + j], u[i2][ww + j], acc);
            res[ww] = acc;
        }

        float4* dst = (float4*)(op + h * WOUT + w0);
        dst[0] = make_float4(res[0], res[1], res[2], res[3]);
        dst[1] = make_float4(res[4], res[5], res[6], res[7]);
    }
}

// ---------------------------------------------------------------------------
// GEMM via mma.sync (HMMA) split-bf16 3-pass, ldmatrix fragment loads,
// register double-buffered chunk prefetch. Block 128(o) x 128(p), 8 warps.
// ---------------------------------------------------------------------------
#define APAD 40    // A smem row stride (bf16): 80 B -> LDSM conflict-free
#define BPAD 136   // B smem row stride (u16): 272 B -> LDSM conflict-free

__device__ __forceinline__ uint32_t smem_u32(const void* p) {
    uint32_t a;
    asm("{ .reg .u64 t; cvta.to.shared.u64 t, %1; cvt.u32.u64 %0, t; }" : "=r"(a) : "l"(p));
    return a;
}
__device__ __forceinline__ void mma_bf16(float* d, const uint32_t* a, const uint32_t* b) {
    asm volatile(
        "mma.sync.aligned.m16n8k16.row.col.f32.bf16.bf16.f32 "
        "{%0,%1,%2,%3}, {%4,%5,%6,%7}, {%8,%9}, {%0,%1,%2,%3};"
        : "+f"(d[0]), "+f"(d[1]), "+f"(d[2]), "+f"(d[3])
        : "r"(a[0]), "r"(a[1]), "r"(a[2]), "r"(a[3]), "r"(b[0]), "r"(b[1]));
}
__device__ __forceinline__ void ldsm_x4(uint32_t* r, uint32_t addr) {
    asm volatile("ldmatrix.sync.aligned.m8n8.x4.shared.b16 {%0,%1,%2,%3}, [%4];"
        : "=r"(r[0]), "=r"(r[1]), "=r"(r[2]), "=r"(r[3]) : "r"(addr));
}
__device__ __forceinline__ void ldsm_x4_t(uint32_t* r, uint32_t addr) {
    asm volatile("ldmatrix.sync.aligned.m8n8.x4.trans.shared.b16 {%0,%1,%2,%3}, [%4];"
        : "=r"(r[0]), "=r"(r[1]), "=r"(r[2]), "=r"(r[3]) : "r"(addr));
}

__global__ __launch_bounds__(256) void gemm_kernel(float* __restrict__ out) {
    __shared__ __align__(16) __nv_bfloat16 Ash[128 * APAD];   // 10240 B
    __shared__ __align__(16) __nv_bfloat16 Als[128 * APAD];   // 10240 B
    __shared__ __align__(16) unsigned short Bhs[32 * BPAD];   //  8704 B
    __shared__ __align__(16) unsigned short Bls[32 * BPAD];   //  8704 B

    int tid  = threadIdx.x;
    int lane = tid & 31;
    int wid  = tid >> 5;

    int b  = blockIdx.x / (NPIX / 128);              // 150 p-tiles per batch
    int p0 = (blockIdx.x - b * (NPIX / 128)) * 128;

    const float* dwp = g_dw + (size_t)b * CIN * NPIX + p0;

    int mw = (wid >> 2) * 64;
    int nw = (wid & 3) * 32;
    int g  = lane >> 2;
    int q  = lane & 3;

    // loader decomposition (A)
    int oA = tid >> 1;                               // 0..127  (2 seg/row of 4)
    int qA0 = (tid & 1) * 2;                         // seg 0/2
    // loader decomposition (B)
    int cB  = tid >> 3;                              // 0..31
    int pB  = (tid & 7) * 16;                        // 4 float4 per thread, stride 4

    // ldmatrix lane addresses
    int lrow = lane & 15;
    int lhi  = (lane >> 4) * 8;
    uint32_t aA_base = smem_u32(Ash) + ((mw + lrow) * APAD + lhi) * 2;
    uint32_t aL_base = smem_u32(Als) + ((mw + lrow) * APAD + lhi) * 2;
    uint32_t bH_base = smem_u32(Bhs) + (lrow * BPAD + nw + lhi) * 2;
    uint32_t bL_base = smem_u32(Bls) + (lrow * BPAD + nw + lhi) * 2;

    float acc[4][4][4];
#pragma unroll
    for (int i = 0; i < 4; i++)
#pragma unroll
        for (int j = 0; j < 4; j++)
#pragma unroll
            for (int k = 0; k < 4; k++) acc[i][j][k] = 0.0f;

    // ---- prefetch chunk 0 into registers ----
    uint4 rAh[2], rAl[2];
    float4 rB[4];
    {
        size_t goff = (size_t)oA * 512 + (size_t)qA0 * 16;
#pragma unroll
        for (int i2 = 0; i2 < 2; i2++) {
            rAh[i2] = *(const uint4*)((const char*)g_Ah + goff + i2 * 16);
            rAl[i2] = *(const uint4*)((const char*)g_Al + goff + i2 * 16);
        }
#pragma unroll
        for (int i2 = 0; i2 < 4; i2++)
            rB[i2] = *(const float4*)(dwp + (size_t)cB * NPIX + pB + i2 * 4);
    }

    for (int ck = 0; ck < CIN / 32; ++ck) {
        // ---- store prefetched chunk to smem (convert B) ----
        {
            char* dA = (char*)Ash + oA * (APAD * 2) + qA0 * 16;
            char* dL = (char*)Als + oA * (APAD * 2) + qA0 * 16;
            *(uint4*)dA = rAh[0];  *(uint4*)(dA + 16) = rAh[1];
            *(uint4*)dL = rAl[0];  *(uint4*)(dL + 16) = rAl[1];
#pragma unroll
            for (int i2 = 0; i2 < 4; i2++) {
                float vv[4] = {rB[i2].x, rB[i2].y, rB[i2].z, rB[i2].w};
                uint32_t h[4], l[4];
#pragma unroll
                for (int j = 0; j < 4; j++) {
                    __nv_bfloat16 hh = __float2bfloat16(vv[j]);
                    __nv_bfloat16 ll = __float2bfloat16(vv[j] - __bfloat162float(hh));
                    h[j] = (uint32_t)__bfloat16_as_ushort(hh);
                    l[j] = (uint32_t)__bfloat16_as_ushort(ll);
                }
                *(uint2*)&Bhs[cB * BPAD + pB + i2 * 4] =
                    make_uint2(h[0] | (h[1] << 16), h[2] | (h[3] << 16));
                *(uint2*)&Bls[cB * BPAD + pB + i2 * 4] =
                    make_uint2(l[0] | (l[1] << 16), l[2] | (l[3] << 16));
            }
        }
        __syncthreads();

        // ---- prefetch next chunk during compute ----
        if (ck + 1 < CIN / 32) {
            size_t goff = (size_t)oA * 512 + (size_t)(ck + 1) * 64 + (size_t)qA0 * 16;
#pragma unroll
            for (int i2 = 0; i2 < 2; i2++) {
                rAh[i2] = *(const uint4*)((const char*)g_Ah + goff + i2 * 16);
                rAl[i2] = *(const uint4*)((const char*)g_Al + goff + i2 * 16);
            }
#pragma unroll
            for (int i2 = 0; i2 < 4; i2++)
                rB[i2] = *(const float4*)(dwp + (size_t)((ck + 1) * 32 + cB) * NPIX + pB + i2 * 4);
        }

        // ---- compute: 2 k16 steps ----
#pragma unroll
        for (int kk = 0; kk < 32; kk += 16) {
            uint32_t bh[4][2], bl[4][2];
#pragma unroll
            for (int t = 0; t < 2; t++) {
                uint32_t r[4];
                ldsm_x4_t(r, bH_base + (kk * BPAD + t * 16) * 2);
                bh[t * 2][0] = r[0]; bh[t * 2][1] = r[1];
                bh[t * 2 + 1][0] = r[2]; bh[t * 2 + 1][1] = r[3];
                ldsm_x4_t(r, bL_base + (kk * BPAD + t * 16) * 2);
                bl[t * 2][0] = r[0]; bl[t * 2][1] = r[1];
                bl[t * 2 + 1][0] = r[2]; bl[t * 2 + 1][1] = r[3];
            }

#pragma unroll
            for (int mt = 0; mt < 4; mt++) {
                uint32_t ah[4], al[4];
                ldsm_x4(ah, aA_base + (mt * 16 * APAD + kk) * 2);
                ldsm_x4(al, aL_base + (mt * 16 * APAD + kk) * 2);
#pragma unroll
                for (int nt = 0; nt < 4; nt++)
                    mma_bf16(acc[mt][nt], ah, bh[nt]);
#pragma unroll
                for (int nt = 0; nt < 4; nt++)
                    mma_bf16(acc[mt][nt], al, bh[nt]);
#pragma unroll
                for (int nt = 0; nt < 4; nt++)
                    mma_bf16(acc[mt][nt], ah, bl[nt]);
            }
        }
        __syncthreads();
    }

    // ---- epilogue ----
    float* base = out + (size_t)b * COUT * NPIX + p0;
#pragma unroll
    for (int mt = 0; mt < 4; mt++) {
#pragma unroll
        for (int nt = 0; nt < 4; nt++) {
            int m = mw + mt * 16 + g;
            int n = nw + nt * 8 + q * 2;
            *(float2*)&base[(size_t)m * NPIX + n] =
                make_float2(acc[mt][nt][0], acc[mt][nt][1]);
            *(float2*)&base[(size_t)(m + 8) * NPIX + n] =
                make_float2(acc[mt][nt][2], acc[mt][nt][3]);
        }
    }
}

// ---------------------------------------------------------------------------
// Launch
// ---------------------------------------------------------------------------
extern "C" void kernel_launch(void* const* d_in, const int* in_sizes, int n_in,
                              void* d_out, int out_size) {
    const float* x   = (const float*)d_in[0];   // [8,256,60,80]
    const float* wdw = (const float*)d_in[1];   // [256,1,3,3]
    const float* wpw = (const float*)d_in[2];   // [128,256]
    float* out = (float*)d_out;                 // [8,128,120,160]

    pwsplit_kernel<<<128, 256>>>(wpw);
    dw_kernel<<<BATCH * CIN, 256>>>(x, wdw);
    gemm_kernel<<<BATCH * (NPIX / 128), 256>>>(out);
}

// round 11
// speedup vs baseline: 1.0882x; 1.0882x over previous
#include <cuda_runtime.h>
#include <cuda_bf16.h>
#include <cstdint>

#define BATCH 8
#define CIN 256
#define COUT 128
#define HIN 60
#define WIN 80
#define HUP 122
#define HOUT 120
#define WOUT 160
#define NPIX (HOUT*WOUT)   // 19200

#define USW 164            // us row stride (floats), 162 used + pad (16B-aligned rows)
#define DW_SMEM ((HUP*WIN + 62*USW) * 4)   // 39040*... = 122*80*4 + 62*164*4 = 79712 B

// ---------------------------------------------------------------------------
// Device-global scratch
// ---------------------------------------------------------------------------
__device__ __align__(16) float         g_dw[(size_t)BATCH * CIN * NPIX]; // [b][c][p]
__device__ __align__(16) __nv_bfloat16 g_Ah[COUT * CIN];                 // pw hi [o][c]
__device__ __align__(16) __nv_bfloat16 g_Al[COUT * CIN];                 // pw lo [o][c]

// ---------------------------------------------------------------------------
// Kernel: split pointwise weights [o][c] fp32 -> bf16 hi/lo
// ---------------------------------------------------------------------------
__global__ void pwsplit_kernel(const float* __restrict__ pw) {
    int i = blockIdx.x * 256 + threadIdx.x;          // 0..32767
    float v = pw[i];
    __nv_bfloat16 h = __float2bfloat16(v);
    __nv_bfloat16 l = __float2bfloat16(v - __bfloat162float(h));
    g_Ah[i] = h;
    g_Al[i] = l;
}

// ---------------------------------------------------------------------------
// Kernel: bilinear upsample (align_corners) + 3x3 depthwise VALID
// Two-stage: vs = vertical lerp [122x80]; us = full upsample half-plane
// [62x164]; conv reads us via aligned float4 (conflict-free).
// ---------------------------------------------------------------------------
__global__ __launch_bounds__(256) void dw_kernel(const float* __restrict__ x,
                                                 const float* __restrict__ wdw) {
    extern __shared__ float dyn[];
    float* vs = dyn;                                 // 122*80
    float* us = dyn + HUP * WIN;                     // 62*164
    __shared__ float fxs[162];
    __shared__ int   x0s[162];

    int bc = blockIdx.x;
    int c  = bc & (CIN - 1);
    const float* xp = x + (size_t)bc * (HIN * WIN);
    float* op = g_dw + (size_t)bc * NPIX;
    int tid = threadIdx.x;

    const float SY = (float)(59.0 / 121.0);
    const float SX = (float)(79.0 / 161.0);

    // horizontal interp table (clamped)
    if (tid < 162) {
        float wx  = tid * SX;
        int   x0  = (int)floorf(wx);
        if (x0 > WIN - 2) x0 = WIN - 2;
        fxs[tid] = wx - (float)x0;
        x0s[tid] = x0;
    }

    // stage 1: vertical interpolation into vs
    for (int i = tid; i < HUP * WIN; i += 256) {
        int rr = i / WIN;
        int xc = i - rr * WIN;
        float hy  = rr * SY;
        float y0f = floorf(hy);
        int   y0  = (int)y0f;
        float fy  = hy - y0f;
        int   y1  = y0 + 1; if (y1 > HIN - 1) y1 = HIN - 1;
        float a  = xp[y0 * WIN + xc];
        float b2 = xp[y1 * WIN + xc];
        vs[i] = a + fy * (b2 - a);
    }

    float kd[9];
#pragma unroll
    for (int t = 0; t < 9; t++) kd[t] = __ldg(wdw + c * 9 + t);

    __syncthreads();

    // two halves: out rows [0,60) use up rows 0..61; [60,120) use 60..121
#pragma unroll
    for (int half = 0; half < 2; half++) {
        int h_base = half * 60;

        // stage 2: horizontal lerp -> us[r][cc], r = up row h_base + r
        for (int i = tid; i < 62 * 162; i += 256) {
            int r  = i / 162;
            int cc = i - r * 162;
            const float* vr = vs + (h_base + r) * WIN;
            int   x0 = x0s[cc];
            float fx = fxs[cc];
            float a  = vr[x0];
            float b2 = vr[x0 + 1];
            us[r * USW + cc] = a + fx * (b2 - a);
        }
        __syncthreads();

        // stage 3: 3x3 conv, 8-px strips, float4 loads from us
        for (int s = tid; s < 1200; s += 256) {
            int h  = s / 20;                         // 0..59 local out row
            int w0 = (s - h * 20) * 8;

            float4 row[3][3];
#pragma unroll
            for (int i2 = 0; i2 < 3; i2++) {
                const float4* ur = (const float4*)(us + (h + i2) * USW + w0);
                row[i2][0] = ur[0];
                row[i2][1] = ur[1];
                row[i2][2] = ur[2];
            }

            float u[3][12];
#pragma unroll
            for (int i2 = 0; i2 < 3; i2++) {
                u[i2][0] = row[i2][0].x;  u[i2][1] = row[i2][0].y;
                u[i2][2] = row[i2][0].z;  u[i2][3] = row[i2][0].w;
                u[i2][4] = row[i2][1].x;  u[i2][5] = row[i2][1].y;
                u[i2][6] = row[i2][1].z;  u[i2][7] = row[i2][1].w;
                u[i2][8] = row[i2][2].x;  u[i2][9] = row[i2][2].y;
                u[i2][10] = row[i2][2].z; u[i2][11] = row[i2][2].w;
            }

            float res[8];
#pragma unroll
            for (int ww = 0; ww < 8; ww++) {
                float acc = 0.0f;
#pragma unroll
                for (int i2 = 0; i2 < 3; i2++)
#pragma unroll
                    for (int j = 0; j < 3; j++)
                        acc = fmaf(kd[i2 * 3 + j], u[i2][ww + j], acc);
                res[ww] = acc;
            }

            float4* dst = (float4*)(op + (h_base + h) * WOUT + w0);
            dst[0] = make_float4(res[0], res[1], res[2], res[3]);
            dst[1] = make_float4(res[4], res[5], res[6], res[7]);
        }
        __syncthreads();                             // us reused next half
    }
}

// ---------------------------------------------------------------------------
// GEMM via mma.sync (HMMA) split-bf16 3-pass — EXACT R6 version (242.1 us).
// Block 128(o) x 128(p), 8 warps, warp tile 64x32, K chunks of 32.
// ---------------------------------------------------------------------------
#define APAD 40    // A smem row stride (elems): 32 + 8 pad -> conflict-free
#define BPAD 136   // B smem row stride (elems): 128 + 8 pad

__device__ __forceinline__ void mma_bf16(float* d, const uint32_t* a, const uint32_t* b) {
    asm volatile(
        "mma.sync.aligned.m16n8k16.row.col.f32.bf16.bf16.f32 "
        "{%0,%1,%2,%3}, {%4,%5,%6,%7}, {%8,%9}, {%0,%1,%2,%3};"
        : "+f"(d[0]), "+f"(d[1]), "+f"(d[2]), "+f"(d[3])
        : "r"(a[0]), "r"(a[1]), "r"(a[2]), "r"(a[3]), "r"(b[0]), "r"(b[1]));
}

__global__ __launch_bounds__(256) void gemm_kernel(float* __restrict__ out) {
    __shared__ __nv_bfloat16 Ash[128 * APAD];        // 10240 B
    __shared__ __nv_bfloat16 Als[128 * APAD];        // 10240 B
    __shared__ unsigned short Bhs[32 * BPAD];        //  8704 B
    __shared__ unsigned short Bls[32 * BPAD];        //  8704 B

    int tid  = threadIdx.x;
    int lane = tid & 31;
    int wid  = tid >> 5;

    int b  = blockIdx.x / (NPIX / 128);              // NPIX/128 = 150
    int p0 = (blockIdx.x - b * (NPIX / 128)) * 128;

    const float* dwp = g_dw + (size_t)b * CIN * NPIX + p0;

    int mw = (wid >> 2) * 64;                        // warp M offset
    int nw = (wid & 3) * 32;                         // warp N offset
    int g  = lane >> 2;                              // group id
    int q  = lane & 3;                               // thread-in-group

    float acc[4][4][4];
#pragma unroll
    for (int i = 0; i < 4; i++)
#pragma unroll
        for (int j = 0; j < 4; j++)
#pragma unroll
            for (int k = 0; k < 4; k++) acc[i][j][k] = 0.0f;

    for (int ck = 0; ck < CIN / 32; ++ck) {
        __syncthreads();                             // protect prev-iter reads

        // --- load A chunk [128 o][32 k] bf16 hi+lo (coalesced 16B) ---
#pragma unroll
        for (int i = 0; i < 2; i++) {
            int idx = tid + i * 256;                 // 0..511 uint4 segments
            int o = idx >> 2, qq = idx & 3;
            size_t goff = (size_t)o * 512 + (size_t)ck * 64 + qq * 16;
            uint4 vh = *(const uint4*)((const char*)g_Ah + goff);
            uint4 vl = *(const uint4*)((const char*)g_Al + goff);
            *(uint4*)((char*)Ash + o * (APAD * 2) + qq * 16) = vh;
            *(uint4*)((char*)Als + o * (APAD * 2) + qq * 16) = vl;
        }

        // --- load B chunk [32 c][128 p] fp32, convert to bf16 hi/lo ---
#pragma unroll
        for (int i = 0; i < 4; i++) {
            int idx = tid + i * 256;                 // 0..1023 float4 segments
            int c  = idx >> 5;
            int p4 = (idx & 31) * 4;
            float4 v = *(const float4*)(dwp + (size_t)(ck * 32 + c) * NPIX + p4);
            float vv[4] = {v.x, v.y, v.z, v.w};
            uint32_t h[4], l[4];
#pragma unroll
            for (int j = 0; j < 4; j++) {
                __nv_bfloat16 hh = __float2bfloat16(vv[j]);
                __nv_bfloat16 ll = __float2bfloat16(vv[j] - __bfloat162float(hh));
                h[j] = (uint32_t)__bfloat16_as_ushort(hh);
                l[j] = (uint32_t)__bfloat16_as_ushort(ll);
            }
            *(uint2*)&Bhs[c * BPAD + p4] =
                make_uint2(h[0] | (h[1] << 16), h[2] | (h[3] << 16));
            *(uint2*)&Bls[c * BPAD + p4] =
                make_uint2(l[0] | (l[1] << 16), l[2] | (l[3] << 16));
        }
        __syncthreads();

        // --- compute: 2 k16 steps per chunk ---
#pragma unroll
        for (int kk = 0; kk < 32; kk += 16) {
            int k0 = kk + q * 2;

            // B fragments (hi & lo), 4 n-tiles
            uint32_t bh[4][2], bl[4][2];
#pragma unroll
            for (int nt = 0; nt < 4; nt++) {
                int n = nw + nt * 8 + g;
                bh[nt][0] = (uint32_t)Bhs[k0 * BPAD + n] |
                            ((uint32_t)Bhs[(k0 + 1) * BPAD + n] << 16);
                bh[nt][1] = (uint32_t)Bhs[(k0 + 8) * BPAD + n] |
                            ((uint32_t)Bhs[(k0 + 9) * BPAD + n] << 16);
                bl[nt][0] = (uint32_t)Bls[k0 * BPAD + n] |
                            ((uint32_t)Bls[(k0 + 1) * BPAD + n] << 16);
                bl[nt][1] = (uint32_t)Bls[(k0 + 8) * BPAD + n] |
                            ((uint32_t)Bls[(k0 + 9) * BPAD + n] << 16);
            }

            // A-hi fragments, 4 m-tiles
            uint32_t ah[4][4];
#pragma unroll
            for (int mt = 0; mt < 4; mt++) {
                int m = mw + mt * 16 + g;
                ah[mt][0] = *(const uint32_t*)&Ash[m * APAD + k0];
                ah[mt][1] = *(const uint32_t*)&Ash[(m + 8) * APAD + k0];
                ah[mt][2] = *(const uint32_t*)&Ash[m * APAD + k0 + 8];
                ah[mt][3] = *(const uint32_t*)&Ash[(m + 8) * APAD + k0 + 8];
            }

            // pass 1: Ah * Bh
#pragma unroll
            for (int mt = 0; mt < 4; mt++)
#pragma unroll
                for (int nt = 0; nt < 4; nt++)
                    mma_bf16(acc[mt][nt], ah[mt], bh[nt]);

            // pass 2: Al * Bh
            uint32_t al[4][4];
#pragma unroll
            for (int mt = 0; mt < 4; mt++) {
                int m = mw + mt * 16 + g;
                al[mt][0] = *(const uint32_t*)&Als[m * APAD + k0];
                al[mt][1] = *(const uint32_t*)&Als[(m + 8) * APAD + k0];
                al[mt][2] = *(const uint32_t*)&Als[m * APAD + k0 + 8];
                al[mt][3] = *(const uint32_t*)&Als[(m + 8) * APAD + k0 + 8];
            }
#pragma unroll
            for (int mt = 0; mt < 4; mt++)
#pragma unroll
                for (int nt = 0; nt < 4; nt++)
                    mma_bf16(acc[mt][nt], al[mt], bh[nt]);

            // pass 3: Ah * Bl
#pragma unroll
            for (int mt = 0; mt < 4; mt++)
#pragma unroll
                for (int nt = 0; nt < 4; nt++)
                    mma_bf16(acc[mt][nt], ah[mt], bl[nt]);
        }
    }

    // --- epilogue ---
    float* base = out + (size_t)b * COUT * NPIX + p0;
#pragma unroll
    for (int mt = 0; mt < 4; mt++) {
#pragma unroll
        for (int nt = 0; nt < 4; nt++) {
            int m = mw + mt * 16 + g;
            int n = nw + nt * 8 + q * 2;
            *(float2*)&base[(size_t)m * NPIX + n] =
                make_float2(acc[mt][nt][0], acc[mt][nt][1]);
            *(float2*)&base[(size_t)(m + 8) * NPIX + n] =
                make_float2(acc[mt][nt][2], acc[mt][nt][3]);
        }
    }
}

// ---------------------------------------------------------------------------
// Launch
// ---------------------------------------------------------------------------
extern "C" void kernel_launch(void* const* d_in, const int* in_sizes, int n_in,
                              void* d_out, int out_size) {
    const float* x   = (const float*)d_in[0];   // [8,256,60,80]
    const float* wdw = (const float*)d_in[1];   // [256,1,3,3]
    const float* wpw = (const float*)d_in[2];   // [128,256]
    float* out = (float*)d_out;                 // [8,128,120,160]

    cudaFuncSetAttribute(dw_kernel, cudaFuncAttributeMaxDynamicSharedMemorySize, DW_SMEM);

    pwsplit_kernel<<<128, 256>>>(wpw);
    dw_kernel<<<BATCH * CIN, 256, DW_SMEM>>>(x, wdw);
    gemm_kernel<<<BATCH * (NPIX / 128), 256>>>(out);
}